// round 12
// baseline (speedup 1.0000x reference)
#include <cuda_runtime.h>
#include <cuda_fp16.h>
#include <math.h>
#include <stdint.h>

#define N_TOK 1024
#define HDIM  1024
#define IDIM  1024
#define NEXP  32
#define TOPK  4
#define NSLOT (N_TOK*TOPK)

#define BM 64
#define BN 128
#define BK 64
#define NK 16            // 1024 / 64

// dynamic smem (bytes from 1024-aligned base)
#define AS_OFF(s) ((s)*8192)               // 2 x 8KB A tiles (fp16 64x64)
#define BS_OFF(s) (16384 + (s)*16384)      // 2 x 16KB decoded B tiles (fp16 128x64)
#define DSMEM_BYTES (49152 + 1024)

// ---------------- device scratch ----------------
__device__ __half g_t[N_TOK*HDIM];
__device__ __half g_a[NSLOT*IDIM];
__device__ int    g_counts[NEXP];
__device__ int    g_offsets[NEXP+1];
__device__ int    g_topidx[NSLOT];
__device__ float  g_topw[NSLOT];
__device__ int    g_slot_tok[NSLOT];
__device__ float  g_slot_w[NSLOT];

// ---------------- helpers ----------------
__device__ __forceinline__ uint32_t smem_u32(const void* p) {
    uint32_t a;
    asm("{ .reg .u64 t; cvta.to.shared.u64 t, %1; cvt.u32.u64 %0, t; }" : "=r"(a) : "l"(p));
    return a;
}
__device__ __forceinline__ void cp16(uint32_t dst, const void* src) {
    asm volatile("cp.async.cg.shared.global [%0], [%1], 16;" :: "r"(dst), "l"(src));
}
#define CP_COMMIT() asm volatile("cp.async.commit_group;" ::: "memory")
#define CP_WAIT0()  asm volatile("cp.async.wait_group 0;" ::: "memory")

__device__ __forceinline__ uint32_t prmt(uint32_t a, uint32_t b, uint32_t sel) {
    uint32_t r; asm("prmt.b32 %0,%1,%2,%3;" : "=r"(r) : "r"(a), "r"(b), "r"(sel)); return r;
}
__device__ __forceinline__ uint32_t hmul2b(uint32_t a, uint32_t b) {
    uint32_t r; asm("mul.rn.f16x2 %0,%1,%2;" : "=r"(r) : "r"(a), "r"(b)); return r;
}
__device__ __forceinline__ void ldsm4(uint32_t& r0, uint32_t& r1, uint32_t& r2, uint32_t& r3,
                                      uint32_t addr) {
    asm volatile("ldmatrix.sync.aligned.m8n8.x4.shared.b16 {%0,%1,%2,%3}, [%4];"
        : "=r"(r0), "=r"(r1), "=r"(r2), "=r"(r3) : "r"(addr));
}
__device__ __forceinline__ void mma_fp16(float c[4], const uint32_t a[4], const uint32_t b[2]) {
    asm volatile("mma.sync.aligned.m16n8k16.row.col.f32.f16.f16.f32 "
        "{%0,%1,%2,%3}, {%4,%5,%6,%7}, {%8,%9}, {%0,%1,%2,%3};"
        : "+f"(c[0]), "+f"(c[1]), "+f"(c[2]), "+f"(c[3])
        : "r"(a[0]), "r"(a[1]), "r"(a[2]), "r"(a[3]), "r"(b[0]), "r"(b[1]));
}
__device__ __forceinline__ unsigned swz(unsigned byte) {
    return byte ^ ((byte >> 3) & 0x70u);
}

// PRMT fp4 magnitude tables: high bytes of fp16 {0,.5,1,1.5,2,3,4,6}
#define TLO 0x3E3C3800u
#define THI 0x46444240u

// decode 4 raw ints (8 fp4 values) -> uint4 of 4 fp16x2, scaled (exact)
__device__ __forceinline__ uint4 dec8(uint4 raw, uint32_t sc2) {
    uint32_t t0 = prmt(raw.x, raw.y, 0x0040u);
    uint32_t t1 = prmt(raw.z, raw.w, 0x0040u);
    uint32_t b4 = prmt(t0, t1, 0x5410u);        // 8 nibbles packed
    uint32_t m01 = prmt(TLO, THI, b4 & 0x7777u);
    uint32_t m23 = prmt(TLO, THI, (b4 >> 16) & 0x7777u);
    uint32_t sgnO = prmt(b4, b4, 0xBA98u);      // odd-nibble sign byte-masks
    uint32_t be = b4 << 4;
    uint32_t sgnE = prmt(be, be, 0xBA98u);      // even-nibble sign byte-masks
    uint4 o;
    o.x = hmul2b(prmt(m01, 0u, 0x1404u) | (prmt(sgnE, sgnO, 0x4000u) & 0x80008000u), sc2);
    o.y = hmul2b(prmt(m01, 0u, 0x3424u) | (prmt(sgnE, sgnO, 0x5010u) & 0x80008000u), sc2);
    o.z = hmul2b(prmt(m23, 0u, 0x1404u) | (prmt(sgnE, sgnO, 0x6020u) & 0x80008000u), sc2);
    o.w = hmul2b(prmt(m23, 0u, 0x3424u) | (prmt(sgnE, sgnO, 0x7030u) & 0x80008000u), sc2);
    return o;
}

// ---------------- k0: zero counters ----------------
__global__ void k0_zero() {
    int i = threadIdx.x;
    if (i < NEXP) g_counts[i] = 0;
}

// ---------------- k1: rmsnorm + residual + gate + top4 ----------------
__global__ __launch_bounds__(256) void k1_norm_gate(
    const float* __restrict__ x, const float* __restrict__ norm_w,
    const float* __restrict__ gate_w, const float* __restrict__ gate_b,
    float* __restrict__ out)
{
    int tok = blockIdx.x;
    int tid = threadIdx.x;
    __shared__ float s_t[HDIM];
    __shared__ float s_red[8];
    __shared__ float s_log[NEXP];

    const float* xr = x + (size_t)tok * HDIM;
    float ss = 0.f;
    for (int i = tid; i < HDIM; i += 256) { float v = xr[i]; ss += v*v; s_t[i] = v; }
    #pragma unroll
    for (int o = 16; o; o >>= 1) ss += __shfl_down_sync(0xffffffffu, ss, o);
    if ((tid & 31) == 0) s_red[tid >> 5] = ss;
    __syncthreads();
    if (tid < 8) {
        float v = s_red[tid];
        #pragma unroll
        for (int o = 4; o; o >>= 1) v += __shfl_down_sync(0xffu, v, o);
        if (tid == 0) s_red[0] = v;
    }
    __syncthreads();
    float scale = rsqrtf(s_red[0] * (1.f / HDIM) + 1e-5f);
    for (int i = tid; i < HDIM; i += 256) {
        float t = s_t[i] * scale * norm_w[i];
        s_t[i] = t;
        g_t[(size_t)tok * HDIM + i] = __float2half_rn(t);
        out[(size_t)tok * HDIM + i] = xr[i];
    }
    __syncthreads();

    int warp = tid >> 5, lane = tid & 31;
    for (int e = warp; e < NEXP; e += 8) {
        const float* gw = gate_w + (size_t)e * HDIM;
        float acc = 0.f;
        for (int i = lane; i < HDIM; i += 32) acc += s_t[i] * gw[i];
        #pragma unroll
        for (int o = 16; o; o >>= 1) acc += __shfl_down_sync(0xffffffffu, acc, o);
        if (lane == 0) s_log[e] = acc + gate_b[e];
    }
    __syncthreads();

    if (tid == 0) {
        int idx[TOPK]; float val[TOPK];
        unsigned mask = 0;
        #pragma unroll
        for (int k = 0; k < TOPK; k++) {
            float best = -1e30f; int bi = 0;
            for (int e = 0; e < NEXP; e++)
                if (!((mask >> e) & 1u) && s_log[e] > best) { best = s_log[e]; bi = e; }
            mask |= 1u << bi; idx[k] = bi; val[k] = best;
        }
        float mx = val[0];
        float se = 0.f;
        #pragma unroll
        for (int k = 0; k < TOPK; k++) { val[k] = expf(val[k] - mx); se += val[k]; }
        float inv = 1.f / se;
        #pragma unroll
        for (int k = 0; k < TOPK; k++) {
            g_topidx[tok*TOPK + k] = idx[k];
            g_topw[tok*TOPK + k]  = val[k] * inv;
            atomicAdd(&g_counts[idx[k]], 1);
        }
    }
}

// ---------------- k2: scan + scatter (single block) ----------------
__global__ __launch_bounds__(1024) void k2_route() {
    __shared__ int s_cur[NEXP];
    __shared__ int s_off[NEXP];
    int tid = threadIdx.x;
    if (tid == 0) {
        int s = 0;
        for (int e = 0; e < NEXP; e++) {
            s_off[e] = s; g_offsets[e] = s; s += g_counts[e];
        }
        g_offsets[NEXP] = s;
    }
    if (tid < NEXP) s_cur[tid] = 0;
    __syncthreads();
    #pragma unroll
    for (int p = 0; p < NSLOT/1024; p++) {
        int i = tid + p*1024;
        int e = g_topidx[i];
        int pos = s_off[e] + atomicAdd(&s_cur[e], 1);
        g_slot_tok[pos] = i >> 2;
        g_slot_w[pos]   = g_topw[i];
    }
}

// ================= k4: fp16 mma grouped GEMM + swiglu (3 CTA/SM, reg-raw) =================
__global__ __launch_bounds__(256, 3) void k4_mlp1(
    const int* __restrict__ blocks, const int* __restrict__ scales,
    const float* __restrict__ bias)
{
    int e  = blockIdx.y;
    int nt = blockIdx.z;                  // 2I/BN = 16
    int cnt = g_counts[e];
    int m0 = blockIdx.x * BM;
    if (m0 >= cnt) return;
    int off = g_offsets[e];

    extern __shared__ char dsm[];
    char* sb = (char*)(((uintptr_t)dsm + 1023) & ~(uintptr_t)1023);
    uint32_t sb32 = smem_u32(sb);
    __shared__ int s_tok[BM];

    const int ROWS = 2*IDIM, GRPS = HDIM/32;
    int tid = threadIdx.x;
    int lane = tid & 31, wid = tid >> 5;
    int wm = wid >> 2, wn = wid & 3;      // 2m x 4n warps, warp tile 32x32

    if (tid < BM) {
        int m = m0 + tid;
        s_tok[tid] = (m < cnt) ? g_slot_tok[off + m] : 0;
    }
    __syncthreads();

    // self-owned raw chunks (warp-coalesced); indices recomputed per use
    int cbase = (tid >> 5)*128 + lane;    // + p*32
    const int* wbase = blocks + ((size_t)e*ROWS + nt*BN)*(size_t)GRPS*16;
    const int* sbase = scales + ((size_t)e*ROWS + nt*BN)*(size_t)GRPS;

    uint4    rw[4];
    uint32_t sclp;

    auto issue = [&](int kt) {
        int s = kt & 1;
        int c = tid & 7, mr = tid >> 3;
        cp16(sb32 + AS_OFF(s) + swz(mr*128 + c*16),
             g_t + (size_t)s_tok[mr]*HDIM + kt*BK + c*8);
        cp16(sb32 + AS_OFF(s) + swz((mr+32)*128 + c*16),
             g_t + (size_t)s_tok[mr+32]*HDIM + kt*BK + c*8);
        uint32_t sp = 0;
        #pragma unroll
        for (int p = 0; p < 4; p++) {
            int ci = cbase + p*32, cn = ci >> 3, cj = ci & 7;
            rw[p] = *(const uint4*)(wbase + (size_t)cn*GRPS*16
                                    + (kt*2 + (cj>>2))*16 + (cj&3)*4);
            sp |= ((uint32_t)__ldg(sbase + cn*GRPS + kt*2 + (cj>>2)) & 0xFFu) << (8*p);
        }
        sclp = sp;
        CP_COMMIT();
    };

    auto decode = [&](int kt) {
        int s = kt & 1;
        #pragma unroll
        for (int p = 0; p < 4; p++) {
            int ci = cbase + p*32, cn = ci >> 3, cj = ci & 7;
            uint32_t sc = (sclp >> (8*p)) & 0xFFu;
            uint32_t sc2 = ((sc - 112u) << 10) * 0x00010001u;
            uint4 o = dec8(rw[p], sc2);
            *(uint4*)(sb + BS_OFF(s) + swz(cn*128 + cj*16)) = o;
        }
    };

    float acc[2][4][4] = {};

    issue(0);
    CP_WAIT0();
    decode(0);

    #pragma unroll 1
    for (int kt = 0; kt < NK; kt++) {
        int s = kt & 1;
        __syncthreads();                  // BS(s), AS(s) visible; other bufs free
        if (kt + 1 < NK) issue(kt + 1);
        uint32_t Ab = sb32 + AS_OFF(s), Bb = sb32 + BS_OFF(s);
        #pragma unroll
        for (int kk = 0; kk < 4; kk++) {
            uint32_t b[4][2];
            {
                int r = lane & 7, kb = (lane >> 3) & 1, nb = lane >> 4;
                #pragma unroll
                for (int g2 = 0; g2 < 2; g2++) {
                    uint32_t ad = Bb + swz((wn*32 + g2*16 + nb*8 + r)*128 + kk*32 + kb*16);
                    ldsm4(b[2*g2][0], b[2*g2][1], b[2*g2+1][0], b[2*g2+1][1], ad);
                }
            }
            uint32_t a[2][4];
            {
                int r = lane & 7, sel = (lane >> 3) & 1, ks = lane >> 4;
                #pragma unroll
                for (int h = 0; h < 2; h++) {
                    uint32_t ad = Ab + swz((wm*32 + h*16 + sel*8 + r)*128 + kk*32 + ks*16);
                    ldsm4(a[h][0], a[h][1], a[h][2], a[h][3], ad);
                }
            }
            #pragma unroll
            for (int h = 0; h < 2; h++)
                #pragma unroll
                for (int g = 0; g < 4; g++)
                    mma_fp16(acc[h][g], a[h], b[g]);
        }
        if (kt + 1 < NK) { CP_WAIT0(); decode(kt + 1); }
    }

    // ---- epilogue: bias + swiglu -> g_a (fp16) ----
    #pragma unroll
    for (int h = 0; h < 2; h++) {
        #pragma unroll
        for (int half = 0; half < 2; half++) {
            int m = m0 + wm*32 + h*16 + (lane >> 2) + half*8;
            if (m >= cnt) continue;
            int slot = off + m;
            #pragma unroll
            for (int g = 0; g < 4; g++) {
                int gcol = nt*BN + wn*32 + g*8 + 2*(lane & 3);
                float hg = acc[h][g][half*2+0] + bias[(size_t)e*ROWS + gcol];
                float hl = acc[h][g][half*2+1] + bias[(size_t)e*ROWS + gcol + 1];
                hg = fminf(hg, 7.f);
                hl = fminf(fmaxf(hl, -7.f), 7.f);
                float aa = hg * (1.f / (1.f + expf(-1.702f * hg))) * (hl + 1.f);
                g_a[(size_t)slot*IDIM + (gcol >> 1)] = __float2half_rn(aa);
            }
        }
    }
}

// ================= k5: fp16 mma grouped GEMM + weighted scatter (3 CTA/SM) =================
__global__ __launch_bounds__(256, 3) void k5_mlp2(
    const int* __restrict__ blocks, const int* __restrict__ scales,
    const float* __restrict__ bias, float* __restrict__ out)
{
    int e  = blockIdx.y;
    int nt = blockIdx.z;                  // H/BN = 8
    int cnt = g_counts[e];
    int m0 = blockIdx.x * BM;
    if (m0 >= cnt) return;
    int off = g_offsets[e];

    extern __shared__ char dsm[];
    char* sb = (char*)(((uintptr_t)dsm + 1023) & ~(uintptr_t)1023);
    uint32_t sb32 = smem_u32(sb);
    __shared__ int   s_tok[BM];
    __shared__ float s_w[BM];

    const int ROWS = HDIM, GRPS = IDIM/32;
    int tid = threadIdx.x;
    int lane = tid & 31, wid = tid >> 5;
    int wm = wid >> 2, wn = wid & 3;

    if (tid < BM) {
        int m = m0 + tid;
        s_tok[tid] = (m < cnt) ? g_slot_tok[off + m] : 0;
        s_w[tid]   = (m < cnt) ? g_slot_w[off + m] : 0.f;
    }
    __syncthreads();

    int cbase = (tid >> 5)*128 + lane;
    const int* wbase = blocks + ((size_t)e*ROWS + nt*BN)*(size_t)GRPS*16;
    const int* sbase = scales + ((size_t)e*ROWS + nt*BN)*(size_t)GRPS;

    uint4    rw[4];
    uint32_t sclp;

    auto issue = [&](int kt) {
        int s = kt & 1;
        int c = tid & 7, mr = tid >> 3;
        int r0 = off + m0 + mr;       if (r0 > NSLOT-1) r0 = NSLOT-1;
        int r1 = off + m0 + mr + 32;  if (r1 > NSLOT-1) r1 = NSLOT-1;
        cp16(sb32 + AS_OFF(s) + swz(mr*128 + c*16), g_a + (size_t)r0*IDIM + kt*BK + c*8);
        cp16(sb32 + AS_OFF(s) + swz((mr+32)*128 + c*16), g_a + (size_t)r1*IDIM + kt*BK + c*8);
        uint32_t sp = 0;
        #pragma unroll
        for (int p = 0; p < 4; p++) {
            int ci = cbase + p*32, cn = ci >> 3, cj = ci & 7;
            rw[p] = *(const uint4*)(wbase + (size_t)cn*GRPS*16
                                    + (kt*2 + (cj>>2))*16 + (cj&3)*4);
            sp |= ((uint32_t)__ldg(sbase + cn*GRPS + kt*2 + (cj>>2)) & 0xFFu) << (8*p);
        }
        sclp = sp;
        CP_COMMIT();
    };

    auto decode = [&](int kt) {
        int s = kt & 1;
        #pragma unroll
        for (int p = 0; p < 4; p++) {
            int ci = cbase + p*32, cn = ci >> 3, cj = ci & 7;
            uint32_t sc = (sclp >> (8*p)) & 0xFFu;
            uint32_t sc2 = ((sc - 112u) << 10) * 0x00010001u;
            uint4 o = dec8(rw[p], sc2);
            *(uint4*)(sb + BS_OFF(s) + swz(cn*128 + cj*16)) = o;
        }
    };

    float acc[2][4][4] = {};

    issue(0);
    CP_WAIT0();
    decode(0);

    #pragma unroll 1
    for (int kt = 0; kt < NK; kt++) {
        int s = kt & 1;
        __syncthreads();
        if (kt + 1 < NK) issue(kt + 1);
        uint32_t Ab = sb32 + AS_OFF(s), Bb = sb32 + BS_OFF(s);
        #pragma unroll
        for (int kk = 0; kk < 4; kk++) {
            uint32_t b[4][2];
            {
                int r = lane & 7, kb = (lane >> 3) & 1, nb = lane >> 4;
                #pragma unroll
                for (int g2 = 0; g2 < 2; g2++) {
                    uint32_t ad = Bb + swz((wn*32 + g2*16 + nb*8 + r)*128 + kk*32 + kb*16);
                    ldsm4(b[2*g2][0], b[2*g2][1], b[2*g2+1][0], b[2*g2+1][1], ad);
                }
            }
            uint32_t a[2][4];
            {
                int r = lane & 7, sel = (lane >> 3) & 1, ks = lane >> 4;
                #pragma unroll
                for (int h = 0; h < 2; h++) {
                    uint32_t ad = Ab + swz((wm*32 + h*16 + sel*8 + r)*128 + kk*32 + ks*16);
                    ldsm4(a[h][0], a[h][1], a[h][2], a[h][3], ad);
                }
            }
            #pragma unroll
            for (int h = 0; h < 2; h++)
                #pragma unroll
                for (int g = 0; g < 4; g++)
                    mma_fp16(acc[h][g], a[h], b[g]);
        }
        if (kt + 1 < NK) { CP_WAIT0(); decode(kt + 1); }
    }

    #pragma unroll
    for (int h = 0; h < 2; h++) {
        #pragma unroll
        for (int half = 0; half < 2; half++) {
            int mi = wm*32 + h*16 + (lane >> 2) + half*8;
            if (m0 + mi >= cnt) continue;
            int tok = s_tok[mi];
            float rwt = s_w[mi];
            #pragma unroll
            for (int g = 0; g < 4; g++) {
                int gcol = nt*BN + wn*32 + g*8 + 2*(lane & 3);
                float y0 = acc[h][g][half*2+0] + bias[(size_t)e*HDIM + gcol];
                float y1 = acc[h][g][half*2+1] + bias[(size_t)e*HDIM + gcol + 1];
                atomicAdd(&out[(size_t)tok*HDIM + gcol],     rwt * y0);
                atomicAdd(&out[(size_t)tok*HDIM + gcol + 1], rwt * y1);
            }
        }
    }
}

// ---------------- launch ----------------
extern "C" void kernel_launch(void* const* d_in, const int* in_sizes, int n_in,
                              void* d_out, int out_size)
{
    const float* x          = (const float*)d_in[0];
    const float* norm_w     = (const float*)d_in[1];
    const float* gate_w     = (const float*)d_in[2];
    const float* gate_b     = (const float*)d_in[3];
    const float* mlp1_bias  = (const float*)d_in[4];
    const float* mlp2_bias  = (const float*)d_in[5];
    const int*   mlp1_blocks= (const int*)d_in[6];
    const int*   mlp1_scales= (const int*)d_in[7];
    const int*   mlp2_blocks= (const int*)d_in[8];
    const int*   mlp2_scales= (const int*)d_in[9];
    float* out = (float*)d_out;

    cudaFuncSetAttribute(k4_mlp1, cudaFuncAttributeMaxDynamicSharedMemorySize, DSMEM_BYTES);
    cudaFuncSetAttribute(k5_mlp2, cudaFuncAttributeMaxDynamicSharedMemorySize, DSMEM_BYTES);

    k0_zero<<<1, 32>>>();
    k1_norm_gate<<<N_TOK, 256>>>(x, norm_w, gate_w, gate_b, out);
    k2_route<<<1, 1024>>>();
    dim3 g4(N_TOK/BM, NEXP, (2*IDIM)/BN);   // (16, 32, 16)
    k4_mlp1<<<g4, 256, DSMEM_BYTES>>>(mlp1_blocks, mlp1_scales, mlp1_bias);
    dim3 g5(N_TOK/BM, NEXP, HDIM/BN);       // (16, 32, 8)
    k5_mlp2<<<g5, 256, DSMEM_BYTES>>>(mlp2_blocks, mlp2_scales, mlp2_bias, out);
}

// round 13
// speedup vs baseline: 1.0670x; 1.0670x over previous
#include <cuda_runtime.h>
#include <cuda_fp16.h>
#include <math.h>
#include <stdint.h>

#define N_TOK 1024
#define HDIM  1024
#define IDIM  1024
#define NEXP  32
#define TOPK  4
#define NSLOT (N_TOK*TOPK)

#define BM 128           // 2 x 64-row subtiles sharing decoded B
#define BN 128
#define BK 64
#define NK 16            // 1024 / 64

// dynamic smem (bytes from 1024-aligned base)
#define AS_OFF(s) ((s)*16384)              // 2 x 16KB A tiles (fp16 128x64)
#define BS_OFF(s) (32768 + (s)*16384)      // 2 x 16KB decoded B tiles
#define DSMEM_BYTES (65536 + 1024)

// ---------------- device scratch ----------------
__device__ __half g_t[N_TOK*HDIM];
__device__ __half g_a[NSLOT*IDIM];
__device__ __half g_y[NSLOT*HDIM];         // per-slot mlp2 outputs (+bias), fp16
__device__ int    g_counts[NEXP];
__device__ int    g_offsets[NEXP+1];
__device__ int    g_topidx[NSLOT];
__device__ float  g_topw[NSLOT];
__device__ int    g_slot_tok[NSLOT];
__device__ float  g_slot_w[NSLOT];
__device__ int    g_inv[NSLOT];            // (tok,k) -> slot position

// ---------------- helpers ----------------
__device__ __forceinline__ uint32_t smem_u32(const void* p) {
    uint32_t a;
    asm("{ .reg .u64 t; cvta.to.shared.u64 t, %1; cvt.u32.u64 %0, t; }" : "=r"(a) : "l"(p));
    return a;
}
__device__ __forceinline__ void cp16(uint32_t dst, const void* src) {
    asm volatile("cp.async.cg.shared.global [%0], [%1], 16;" :: "r"(dst), "l"(src));
}
#define CP_COMMIT() asm volatile("cp.async.commit_group;" ::: "memory")
#define CP_WAIT0()  asm volatile("cp.async.wait_group 0;" ::: "memory")

__device__ __forceinline__ uint32_t prmt(uint32_t a, uint32_t b, uint32_t sel) {
    uint32_t r; asm("prmt.b32 %0,%1,%2,%3;" : "=r"(r) : "r"(a), "r"(b), "r"(sel)); return r;
}
__device__ __forceinline__ uint32_t hmul2b(uint32_t a, uint32_t b) {
    uint32_t r; asm("mul.rn.f16x2 %0,%1,%2;" : "=r"(r) : "r"(a), "r"(b)); return r;
}
__device__ __forceinline__ void ldsm4(uint32_t& r0, uint32_t& r1, uint32_t& r2, uint32_t& r3,
                                      uint32_t addr) {
    asm volatile("ldmatrix.sync.aligned.m8n8.x4.shared.b16 {%0,%1,%2,%3}, [%4];"
        : "=r"(r0), "=r"(r1), "=r"(r2), "=r"(r3) : "r"(addr));
}
__device__ __forceinline__ void mma_fp16(float c[4], const uint32_t a[4], const uint32_t b[2]) {
    asm volatile("mma.sync.aligned.m16n8k16.row.col.f32.f16.f16.f32 "
        "{%0,%1,%2,%3}, {%4,%5,%6,%7}, {%8,%9}, {%0,%1,%2,%3};"
        : "+f"(c[0]), "+f"(c[1]), "+f"(c[2]), "+f"(c[3])
        : "r"(a[0]), "r"(a[1]), "r"(a[2]), "r"(a[3]), "r"(b[0]), "r"(b[1]));
}
__device__ __forceinline__ unsigned swz(unsigned byte) {
    return byte ^ ((byte >> 3) & 0x70u);
}

// PRMT fp4 magnitude tables: high bytes of fp16 {0,.5,1,1.5,2,3,4,6}
#define TLO 0x3E3C3800u
#define THI 0x46444240u

// decode 4 raw ints (8 fp4 values) -> uint4 of 4 fp16x2, scaled (exact)
__device__ __forceinline__ uint4 dec8(uint4 raw, uint32_t sc2) {
    uint32_t t0 = prmt(raw.x, raw.y, 0x0040u);
    uint32_t t1 = prmt(raw.z, raw.w, 0x0040u);
    uint32_t b4 = prmt(t0, t1, 0x5410u);        // 8 nibbles packed
    uint32_t m01 = prmt(TLO, THI, b4 & 0x7777u);
    uint32_t m23 = prmt(TLO, THI, (b4 >> 16) & 0x7777u);
    uint32_t sgnO = prmt(b4, b4, 0xBA98u);      // odd-nibble sign byte-masks
    uint32_t be = b4 << 4;
    uint32_t sgnE = prmt(be, be, 0xBA98u);      // even-nibble sign byte-masks
    uint4 o;
    o.x = hmul2b(prmt(m01, 0u, 0x1404u) | (prmt(sgnE, sgnO, 0x4000u) & 0x80008000u), sc2);
    o.y = hmul2b(prmt(m01, 0u, 0x3424u) | (prmt(sgnE, sgnO, 0x5010u) & 0x80008000u), sc2);
    o.z = hmul2b(prmt(m23, 0u, 0x1404u) | (prmt(sgnE, sgnO, 0x6020u) & 0x80008000u), sc2);
    o.w = hmul2b(prmt(m23, 0u, 0x3424u) | (prmt(sgnE, sgnO, 0x7030u) & 0x80008000u), sc2);
    return o;
}

// ---------------- k0: zero counters ----------------
__global__ void k0_zero() {
    int i = threadIdx.x;
    if (i < NEXP) g_counts[i] = 0;
}

// ---------------- k1: rmsnorm + residual + gate + top4 ----------------
__global__ __launch_bounds__(256) void k1_norm_gate(
    const float* __restrict__ x, const float* __restrict__ norm_w,
    const float* __restrict__ gate_w, const float* __restrict__ gate_b,
    float* __restrict__ out)
{
    int tok = blockIdx.x;
    int tid = threadIdx.x;
    __shared__ float s_t[HDIM];
    __shared__ float s_red[8];
    __shared__ float s_log[NEXP];

    const float* xr = x + (size_t)tok * HDIM;
    float ss = 0.f;
    for (int i = tid; i < HDIM; i += 256) { float v = xr[i]; ss += v*v; s_t[i] = v; }
    #pragma unroll
    for (int o = 16; o; o >>= 1) ss += __shfl_down_sync(0xffffffffu, ss, o);
    if ((tid & 31) == 0) s_red[tid >> 5] = ss;
    __syncthreads();
    if (tid < 8) {
        float v = s_red[tid];
        #pragma unroll
        for (int o = 4; o; o >>= 1) v += __shfl_down_sync(0xffu, v, o);
        if (tid == 0) s_red[0] = v;
    }
    __syncthreads();
    float scale = rsqrtf(s_red[0] * (1.f / HDIM) + 1e-5f);
    for (int i = tid; i < HDIM; i += 256) {
        float t = s_t[i] * scale * norm_w[i];
        s_t[i] = t;
        g_t[(size_t)tok * HDIM + i] = __float2half_rn(t);
        out[(size_t)tok * HDIM + i] = xr[i];
    }
    __syncthreads();

    int warp = tid >> 5, lane = tid & 31;
    for (int e = warp; e < NEXP; e += 8) {
        const float* gw = gate_w + (size_t)e * HDIM;
        float acc = 0.f;
        for (int i = lane; i < HDIM; i += 32) acc += s_t[i] * gw[i];
        #pragma unroll
        for (int o = 16; o; o >>= 1) acc += __shfl_down_sync(0xffffffffu, acc, o);
        if (lane == 0) s_log[e] = acc + gate_b[e];
    }
    __syncthreads();

    if (tid == 0) {
        int idx[TOPK]; float val[TOPK];
        unsigned mask = 0;
        #pragma unroll
        for (int k = 0; k < TOPK; k++) {
            float best = -1e30f; int bi = 0;
            for (int e = 0; e < NEXP; e++)
                if (!((mask >> e) & 1u) && s_log[e] > best) { best = s_log[e]; bi = e; }
            mask |= 1u << bi; idx[k] = bi; val[k] = best;
        }
        float mx = val[0];
        float se = 0.f;
        #pragma unroll
        for (int k = 0; k < TOPK; k++) { val[k] = expf(val[k] - mx); se += val[k]; }
        float inv = 1.f / se;
        #pragma unroll
        for (int k = 0; k < TOPK; k++) {
            g_topidx[tok*TOPK + k] = idx[k];
            g_topw[tok*TOPK + k]  = val[k] * inv;
            atomicAdd(&g_counts[idx[k]], 1);
        }
    }
}

// ---------------- k2: scan + scatter (single block) ----------------
__global__ __launch_bounds__(1024) void k2_route() {
    __shared__ int s_cur[NEXP];
    __shared__ int s_off[NEXP];
    int tid = threadIdx.x;
    if (tid == 0) {
        int s = 0;
        for (int e = 0; e < NEXP; e++) {
            s_off[e] = s; g_offsets[e] = s; s += g_counts[e];
        }
        g_offsets[NEXP] = s;
    }
    if (tid < NEXP) s_cur[tid] = 0;
    __syncthreads();
    #pragma unroll
    for (int p = 0; p < NSLOT/1024; p++) {
        int i = tid + p*1024;
        int e = g_topidx[i];
        int pos = s_off[e] + atomicAdd(&s_cur[e], 1);
        g_slot_tok[pos] = i >> 2;
        g_slot_w[pos]   = g_topw[i];
        g_inv[i]        = pos;
    }
}

// ================= k4: dual-subtile fp16 mma GEMM + swiglu =================
__global__ __launch_bounds__(256, 2) void k4_mlp1(
    const int* __restrict__ blocks, const int* __restrict__ scales,
    const float* __restrict__ bias)
{
    int e  = blockIdx.y;
    int nt = blockIdx.z;                  // 2I/BN = 16
    int cnt = g_counts[e];
    int m0 = blockIdx.x * BM;
    if (m0 >= cnt) return;
    bool do2 = (m0 + 64 < cnt);
    int off = g_offsets[e];

    extern __shared__ char dsm[];
    char* sb = (char*)(((uintptr_t)dsm + 1023) & ~(uintptr_t)1023);
    uint32_t sb32 = smem_u32(sb);
    __shared__ int s_tok[BM];

    const int ROWS = 2*IDIM, GRPS = HDIM/32;
    int tid = threadIdx.x;
    int lane = tid & 31, wid = tid >> 5;
    int wm = wid >> 2, wn = wid & 3;

    for (int i = tid; i < BM; i += 256) {
        int m = m0 + i;
        s_tok[i] = (m < cnt) ? g_slot_tok[off + m] : 0;
    }
    __syncthreads();

    int ci[4], cn[4], cj[4];
    #pragma unroll
    for (int p = 0; p < 4; p++) {
        ci[p] = (tid >> 5)*128 + p*32 + lane;
        cn[p] = ci[p] >> 3; cj[p] = ci[p] & 7;
    }
    const int* wbase = blocks + ((size_t)e*ROWS + nt*BN)*(size_t)GRPS*16;
    const int* sbase = scales + ((size_t)e*ROWS + nt*BN)*(size_t)GRPS;

    uint4    rw[4];
    uint32_t scl[4];

    auto issue = [&](int kt) {
        int s = kt & 1;
        int c = tid & 7, mr = tid >> 3;
        cp16(sb32 + AS_OFF(s) + swz(mr*128 + c*16),
             g_t + (size_t)s_tok[mr]*HDIM + kt*BK + c*8);
        cp16(sb32 + AS_OFF(s) + swz((mr+32)*128 + c*16),
             g_t + (size_t)s_tok[mr+32]*HDIM + kt*BK + c*8);
        if (do2) {
            cp16(sb32 + AS_OFF(s) + swz((mr+64)*128 + c*16),
                 g_t + (size_t)s_tok[mr+64]*HDIM + kt*BK + c*8);
            cp16(sb32 + AS_OFF(s) + swz((mr+96)*128 + c*16),
                 g_t + (size_t)s_tok[mr+96]*HDIM + kt*BK + c*8);
        }
        #pragma unroll
        for (int p = 0; p < 4; p++) {
            rw[p] = *(const uint4*)(wbase + (size_t)cn[p]*GRPS*16
                                    + (kt*2 + (cj[p]>>2))*16 + (cj[p]&3)*4);
            scl[p] = (uint32_t)__ldg(sbase + cn[p]*GRPS + kt*2 + (cj[p]>>2));
        }
        CP_COMMIT();
    };

    auto decode = [&](int kt) {
        int s = kt & 1;
        #pragma unroll
        for (int p = 0; p < 4; p++) {
            uint32_t sc2 = ((scl[p] - 112u) << 10) * 0x00010001u;
            uint4 o = dec8(rw[p], sc2);
            *(uint4*)(sb + BS_OFF(s) + swz(cn[p]*128 + cj[p]*16)) = o;
        }
    };

    float acc[2][2][4][4] = {};          // [subtile][h][g][4]

    issue(0);
    CP_WAIT0();
    decode(0);

    #pragma unroll 1
    for (int kt = 0; kt < NK; kt++) {
        int s = kt & 1;
        __syncthreads();
        if (kt + 1 < NK) issue(kt + 1);
        uint32_t Ab = sb32 + AS_OFF(s), Bb = sb32 + BS_OFF(s);
        #pragma unroll
        for (int kk = 0; kk < 4; kk++) {
            uint32_t b[4][2];
            {
                int r = lane & 7, kb = (lane >> 3) & 1, nb = lane >> 4;
                #pragma unroll
                for (int g2 = 0; g2 < 2; g2++) {
                    uint32_t ad = Bb + swz((wn*32 + g2*16 + nb*8 + r)*128 + kk*32 + kb*16);
                    ldsm4(b[2*g2][0], b[2*g2][1], b[2*g2+1][0], b[2*g2+1][1], ad);
                }
            }
            int r = lane & 7, sel = (lane >> 3) & 1, ks = lane >> 4;
            uint32_t a[2][4];
            #pragma unroll
            for (int h = 0; h < 2; h++) {
                uint32_t ad = Ab + swz((wm*32 + h*16 + sel*8 + r)*128 + kk*32 + ks*16);
                ldsm4(a[h][0], a[h][1], a[h][2], a[h][3], ad);
            }
            #pragma unroll
            for (int h = 0; h < 2; h++)
                #pragma unroll
                for (int g = 0; g < 4; g++)
                    mma_fp16(acc[0][h][g], a[h], b[g]);
            if (do2) {
                #pragma unroll
                for (int h = 0; h < 2; h++) {
                    uint32_t ad = Ab + swz((64 + wm*32 + h*16 + sel*8 + r)*128 + kk*32 + ks*16);
                    ldsm4(a[h][0], a[h][1], a[h][2], a[h][3], ad);
                }
                #pragma unroll
                for (int h = 0; h < 2; h++)
                    #pragma unroll
                    for (int g = 0; g < 4; g++)
                        mma_fp16(acc[1][h][g], a[h], b[g]);
            }
        }
        if (kt + 1 < NK) { CP_WAIT0(); decode(kt + 1); }
    }

    // ---- epilogue: bias + swiglu -> g_a (fp16) ----
    #pragma unroll
    for (int t = 0; t < 2; t++) {
        #pragma unroll
        for (int h = 0; h < 2; h++) {
            #pragma unroll
            for (int half = 0; half < 2; half++) {
                int m = m0 + t*64 + wm*32 + h*16 + (lane >> 2) + half*8;
                if (m >= cnt) continue;
                int slot = off + m;
                #pragma unroll
                for (int g = 0; g < 4; g++) {
                    int gcol = nt*BN + wn*32 + g*8 + 2*(lane & 3);
                    float hg = acc[t][h][g][half*2+0] + bias[(size_t)e*ROWS + gcol];
                    float hl = acc[t][h][g][half*2+1] + bias[(size_t)e*ROWS + gcol + 1];
                    hg = fminf(hg, 7.f);
                    hl = fminf(fmaxf(hl, -7.f), 7.f);
                    float aa = hg * (1.f / (1.f + expf(-1.702f * hg))) * (hl + 1.f);
                    g_a[(size_t)slot*IDIM + (gcol >> 1)] = __float2half_rn(aa);
                }
            }
        }
    }
}

// ================= k5: dual-subtile fp16 mma GEMM -> g_y (fp16, no atomics) =================
__global__ __launch_bounds__(256, 2) void k5_mlp2(
    const int* __restrict__ blocks, const int* __restrict__ scales,
    const float* __restrict__ bias)
{
    int e  = blockIdx.y;
    int nt = blockIdx.z;                  // H/BN = 8
    int cnt = g_counts[e];
    int m0 = blockIdx.x * BM;
    if (m0 >= cnt) return;
    bool do2 = (m0 + 64 < cnt);
    int off = g_offsets[e];

    extern __shared__ char dsm[];
    char* sb = (char*)(((uintptr_t)dsm + 1023) & ~(uintptr_t)1023);
    uint32_t sb32 = smem_u32(sb);

    const int ROWS = HDIM, GRPS = IDIM/32;
    int tid = threadIdx.x;
    int lane = tid & 31, wid = tid >> 5;
    int wm = wid >> 2, wn = wid & 3;

    int ci[4], cn[4], cj[4];
    #pragma unroll
    for (int p = 0; p < 4; p++) {
        ci[p] = (tid >> 5)*128 + p*32 + lane;
        cn[p] = ci[p] >> 3; cj[p] = ci[p] & 7;
    }
    const int* wbase = blocks + ((size_t)e*ROWS + nt*BN)*(size_t)GRPS*16;
    const int* sbase = scales + ((size_t)e*ROWS + nt*BN)*(size_t)GRPS;

    uint4    rw[4];
    uint32_t scl[4];

    auto issue = [&](int kt) {
        int s = kt & 1;
        int c = tid & 7, mr = tid >> 3;
        int r0 = off + m0 + mr;       if (r0 > NSLOT-1) r0 = NSLOT-1;
        int r1 = off + m0 + mr + 32;  if (r1 > NSLOT-1) r1 = NSLOT-1;
        cp16(sb32 + AS_OFF(s) + swz(mr*128 + c*16), g_a + (size_t)r0*IDIM + kt*BK + c*8);
        cp16(sb32 + AS_OFF(s) + swz((mr+32)*128 + c*16), g_a + (size_t)r1*IDIM + kt*BK + c*8);
        if (do2) {
            int r2 = off + m0 + mr + 64;  if (r2 > NSLOT-1) r2 = NSLOT-1;
            int r3 = off + m0 + mr + 96;  if (r3 > NSLOT-1) r3 = NSLOT-1;
            cp16(sb32 + AS_OFF(s) + swz((mr+64)*128 + c*16), g_a + (size_t)r2*IDIM + kt*BK + c*8);
            cp16(sb32 + AS_OFF(s) + swz((mr+96)*128 + c*16), g_a + (size_t)r3*IDIM + kt*BK + c*8);
        }
        #pragma unroll
        for (int p = 0; p < 4; p++) {
            rw[p] = *(const uint4*)(wbase + (size_t)cn[p]*GRPS*16
                                    + (kt*2 + (cj[p]>>2))*16 + (cj[p]&3)*4);
            scl[p] = (uint32_t)__ldg(sbase + cn[p]*GRPS + kt*2 + (cj[p]>>2));
        }
        CP_COMMIT();
    };

    auto decode = [&](int kt) {
        int s = kt & 1;
        #pragma unroll
        for (int p = 0; p < 4; p++) {
            uint32_t sc2 = ((scl[p] - 112u) << 10) * 0x00010001u;
            uint4 o = dec8(rw[p], sc2);
            *(uint4*)(sb + BS_OFF(s) + swz(cn[p]*128 + cj[p]*16)) = o;
        }
    };

    float acc[2][2][4][4] = {};

    issue(0);
    CP_WAIT0();
    decode(0);

    #pragma unroll 1
    for (int kt = 0; kt < NK; kt++) {
        int s = kt & 1;
        __syncthreads();
        if (kt + 1 < NK) issue(kt + 1);
        uint32_t Ab = sb32 + AS_OFF(s), Bb = sb32 + BS_OFF(s);
        #pragma unroll
        for (int kk = 0; kk < 4; kk++) {
            uint32_t b[4][2];
            {
                int r = lane & 7, kb = (lane >> 3) & 1, nb = lane >> 4;
                #pragma unroll
                for (int g2 = 0; g2 < 2; g2++) {
                    uint32_t ad = Bb + swz((wn*32 + g2*16 + nb*8 + r)*128 + kk*32 + kb*16);
                    ldsm4(b[2*g2][0], b[2*g2][1], b[2*g2+1][0], b[2*g2+1][1], ad);
                }
            }
            int r = lane & 7, sel = (lane >> 3) & 1, ks = lane >> 4;
            uint32_t a[2][4];
            #pragma unroll
            for (int h = 0; h < 2; h++) {
                uint32_t ad = Ab + swz((wm*32 + h*16 + sel*8 + r)*128 + kk*32 + ks*16);
                ldsm4(a[h][0], a[h][1], a[h][2], a[h][3], ad);
            }
            #pragma unroll
            for (int h = 0; h < 2; h++)
                #pragma unroll
                for (int g = 0; g < 4; g++)
                    mma_fp16(acc[0][h][g], a[h], b[g]);
            if (do2) {
                #pragma unroll
                for (int h = 0; h < 2; h++) {
                    uint32_t ad = Ab + swz((64 + wm*32 + h*16 + sel*8 + r)*128 + kk*32 + ks*16);
                    ldsm4(a[h][0], a[h][1], a[h][2], a[h][3], ad);
                }
                #pragma unroll
                for (int h = 0; h < 2; h++)
                    #pragma unroll
                    for (int g = 0; g < 4; g++)
                        mma_fp16(acc[1][h][g], a[h], b[g]);
            }
        }
        if (kt + 1 < NK) { CP_WAIT0(); decode(kt + 1); }
    }

    // ---- epilogue: bias -> g_y (fp16 half2 stores, coalesced, no atomics) ----
    #pragma unroll
    for (int t = 0; t < 2; t++) {
        #pragma unroll
        for (int h = 0; h < 2; h++) {
            #pragma unroll
            for (int half = 0; half < 2; half++) {
                int mi = t*64 + wm*32 + h*16 + (lane >> 2) + half*8;
                if (m0 + mi >= cnt) continue;
                int slot = off + m0 + mi;
                #pragma unroll
                for (int g = 0; g < 4; g++) {
                    int gcol = nt*BN + wn*32 + g*8 + 2*(lane & 3);
                    float y0 = acc[t][h][g][half*2+0] + bias[(size_t)e*HDIM + gcol];
                    float y1 = acc[t][h][g][half*2+1] + bias[(size_t)e*HDIM + gcol + 1];
                    *(__half2*)(g_y + (size_t)slot*HDIM + gcol) =
                        __floats2half2_rn(y0, y1);
                }
            }
        }
    }
}

// ---------------- k6: weighted combine (out += sum_k w_k * y_k) ----------------
__global__ __launch_bounds__(256) void k6_combine(float* __restrict__ out) {
    int tok = blockIdx.x;
    int tid = threadIdx.x;
    int i4 = tok * TOPK;
    float w0 = g_topw[i4+0], w1 = g_topw[i4+1], w2 = g_topw[i4+2], w3 = g_topw[i4+3];
    const __half2* y0 = (const __half2*)(g_y + (size_t)g_inv[i4+0]*HDIM);
    const __half2* y1 = (const __half2*)(g_y + (size_t)g_inv[i4+1]*HDIM);
    const __half2* y2 = (const __half2*)(g_y + (size_t)g_inv[i4+2]*HDIM);
    const __half2* y3 = (const __half2*)(g_y + (size_t)g_inv[i4+3]*HDIM);
    float* op = out + (size_t)tok*HDIM;
    #pragma unroll
    for (int it = 0; it < HDIM/512; it++) {
        int c2 = tid + it*256;
        float2 v0 = __half22float2(y0[c2]);
        float2 v1 = __half22float2(y1[c2]);
        float2 v2 = __half22float2(y2[c2]);
        float2 v3 = __half22float2(y3[c2]);
        float sx = w0*v0.x + w1*v1.x + w2*v2.x + w3*v3.x;
        float sy = w0*v0.y + w1*v1.y + w2*v2.y + w3*v3.y;
        op[c2*2]   += sx;
        op[c2*2+1] += sy;
    }
}

// ---------------- launch ----------------
extern "C" void kernel_launch(void* const* d_in, const int* in_sizes, int n_in,
                              void* d_out, int out_size)
{
    const float* x          = (const float*)d_in[0];
    const float* norm_w     = (const float*)d_in[1];
    const float* gate_w     = (const float*)d_in[2];
    const float* gate_b     = (const float*)d_in[3];
    const float* mlp1_bias  = (const float*)d_in[4];
    const float* mlp2_bias  = (const float*)d_in[5];
    const int*   mlp1_blocks= (const int*)d_in[6];
    const int*   mlp1_scales= (const int*)d_in[7];
    const int*   mlp2_blocks= (const int*)d_in[8];
    const int*   mlp2_scales= (const int*)d_in[9];
    float* out = (float*)d_out;

    cudaFuncSetAttribute(k4_mlp1, cudaFuncAttributeMaxDynamicSharedMemorySize, DSMEM_BYTES);
    cudaFuncSetAttribute(k5_mlp2, cudaFuncAttributeMaxDynamicSharedMemorySize, DSMEM_BYTES);

    k0_zero<<<1, 32>>>();
    k1_norm_gate<<<N_TOK, 256>>>(x, norm_w, gate_w, gate_b, out);
    k2_route<<<1, 1024>>>();
    dim3 g4(N_TOK/BM, NEXP, (2*IDIM)/BN);   // (8, 32, 16)
    k4_mlp1<<<g4, 256, DSMEM_BYTES>>>(mlp1_blocks, mlp1_scales, mlp1_bias);
    dim3 g5(N_TOK/BM, NEXP, HDIM/BN);       // (8, 32, 8)
    k5_mlp2<<<g5, 256, DSMEM_BYTES>>>(mlp2_blocks, mlp2_scales, mlp2_bias);
    k6_combine<<<N_TOK, 256>>>(out);
}

// round 14
// speedup vs baseline: 1.1038x; 1.0345x over previous
#include <cuda_runtime.h>
#include <cuda_fp16.h>
#include <math.h>
#include <stdint.h>

#define N_TOK 1024
#define HDIM  1024
#define IDIM  1024
#define NEXP  32
#define TOPK  4
#define NSLOT (N_TOK*TOPK)
#define T4    4

#define BM 128           // 2 x 64-row subtiles sharing decoded B
#define BN 128
#define BK 64
#define NK 16            // 1024 / 64

// dynamic smem (bytes from 1024-aligned base)
#define AS_OFF(s) ((s)*16384)              // 2 x 16KB A tiles (fp16 128x64)
#define BS_OFF(s) (32768 + (s)*16384)      // 2 x 16KB decoded B tiles
#define DSMEM_BYTES (65536 + 1024)

// ---------------- device scratch ----------------
__device__ __half g_t[N_TOK*HDIM];
__device__ __half g_a[NSLOT*IDIM];
__device__ int    g_counts[NEXP];
__device__ int    g_offsets[NEXP+1];
__device__ int    g_topidx[NSLOT];
__device__ float  g_topw[NSLOT];
__device__ int    g_slot_tok[NSLOT];
__device__ float  g_slot_w[NSLOT];

// ---------------- helpers ----------------
__device__ __forceinline__ uint32_t smem_u32(const void* p) {
    uint32_t a;
    asm("{ .reg .u64 t; cvta.to.shared.u64 t, %1; cvt.u32.u64 %0, t; }" : "=r"(a) : "l"(p));
    return a;
}
__device__ __forceinline__ void cp16(uint32_t dst, const void* src) {
    asm volatile("cp.async.cg.shared.global [%0], [%1], 16;" :: "r"(dst), "l"(src));
}
#define CP_COMMIT() asm volatile("cp.async.commit_group;" ::: "memory")
#define CP_WAIT0()  asm volatile("cp.async.wait_group 0;" ::: "memory")

__device__ __forceinline__ uint32_t prmt(uint32_t a, uint32_t b, uint32_t sel) {
    uint32_t r; asm("prmt.b32 %0,%1,%2,%3;" : "=r"(r) : "r"(a), "r"(b), "r"(sel)); return r;
}
__device__ __forceinline__ uint32_t hmul2b(uint32_t a, uint32_t b) {
    uint32_t r; asm("mul.rn.f16x2 %0,%1,%2;" : "=r"(r) : "r"(a), "r"(b)); return r;
}
__device__ __forceinline__ void ldsm4(uint32_t& r0, uint32_t& r1, uint32_t& r2, uint32_t& r3,
                                      uint32_t addr) {
    asm volatile("ldmatrix.sync.aligned.m8n8.x4.shared.b16 {%0,%1,%2,%3}, [%4];"
        : "=r"(r0), "=r"(r1), "=r"(r2), "=r"(r3) : "r"(addr));
}
__device__ __forceinline__ void mma_fp16(float c[4], const uint32_t a[4], const uint32_t b[2]) {
    asm volatile("mma.sync.aligned.m16n8k16.row.col.f32.f16.f16.f32 "
        "{%0,%1,%2,%3}, {%4,%5,%6,%7}, {%8,%9}, {%0,%1,%2,%3};"
        : "+f"(c[0]), "+f"(c[1]), "+f"(c[2]), "+f"(c[3])
        : "r"(a[0]), "r"(a[1]), "r"(a[2]), "r"(a[3]), "r"(b[0]), "r"(b[1]));
}
__device__ __forceinline__ unsigned swz(unsigned byte) {
    return byte ^ ((byte >> 3) & 0x70u);
}

// PRMT fp4 magnitude tables: high bytes of fp16 {0,.5,1,1.5,2,3,4,6}
#define TLO 0x3E3C3800u
#define THI 0x46444240u

// decode 4 raw ints (8 fp4 values) -> uint4 of 4 fp16x2, scaled (exact)
__device__ __forceinline__ uint4 dec8(uint4 raw, uint32_t sc2) {
    uint32_t t0 = prmt(raw.x, raw.y, 0x0040u);
    uint32_t t1 = prmt(raw.z, raw.w, 0x0040u);
    uint32_t b4 = prmt(t0, t1, 0x5410u);        // 8 nibbles packed
    uint32_t m01 = prmt(TLO, THI, b4 & 0x7777u);
    uint32_t m23 = prmt(TLO, THI, (b4 >> 16) & 0x7777u);
    uint32_t sgnO = prmt(b4, b4, 0xBA98u);      // odd-nibble sign byte-masks
    uint32_t be = b4 << 4;
    uint32_t sgnE = prmt(be, be, 0xBA98u);      // even-nibble sign byte-masks
    uint4 o;
    o.x = hmul2b(prmt(m01, 0u, 0x1404u) | (prmt(sgnE, sgnO, 0x4000u) & 0x80008000u), sc2);
    o.y = hmul2b(prmt(m01, 0u, 0x3424u) | (prmt(sgnE, sgnO, 0x5010u) & 0x80008000u), sc2);
    o.z = hmul2b(prmt(m23, 0u, 0x1404u) | (prmt(sgnE, sgnO, 0x6020u) & 0x80008000u), sc2);
    o.w = hmul2b(prmt(m23, 0u, 0x3424u) | (prmt(sgnE, sgnO, 0x7030u) & 0x80008000u), sc2);
    return o;
}

// ---------------- k0: zero counters ----------------
__global__ void k0_zero() {
    int i = threadIdx.x;
    if (i < NEXP) g_counts[i] = 0;
}

// ---------------- k1: rmsnorm + residual + gate + top4 (4 tokens/block) ----------------
__global__ __launch_bounds__(256) void k1_norm_gate(
    const float* __restrict__ x, const float* __restrict__ norm_w,
    const float* __restrict__ gate_w, const float* __restrict__ gate_b,
    float* __restrict__ out)
{
    int tb = blockIdx.x * T4;
    int tid = threadIdx.x;
    int warp = tid >> 5, lane = tid & 31;
    __shared__ float s_t[T4][HDIM];
    __shared__ float s_red[T4][8];
    __shared__ float s_log[T4][NEXP];

    float ss[T4] = {};
    #pragma unroll
    for (int t = 0; t < T4; t++) {
        const float* xr = x + (size_t)(tb + t) * HDIM;
        #pragma unroll
        for (int it = 0; it < HDIM/256; it++) {
            int i = tid + it*256;
            float v = xr[i];
            ss[t] += v*v;
            s_t[t][i] = v;
        }
    }
    #pragma unroll
    for (int t = 0; t < T4; t++) {
        float v = ss[t];
        #pragma unroll
        for (int o = 16; o; o >>= 1) v += __shfl_down_sync(0xffffffffu, v, o);
        if (lane == 0) s_red[t][warp] = v;
    }
    __syncthreads();
    if (tid < 32) {
        int t = tid >> 3, sl = tid & 7;
        float v = s_red[t][sl];
        v += __shfl_down_sync(0xffffffffu, v, 4);
        v += __shfl_down_sync(0xffffffffu, v, 2);
        v += __shfl_down_sync(0xffffffffu, v, 1);
        if (sl == 0) s_red[t][0] = v;
    }
    __syncthreads();
    float scale[T4];
    #pragma unroll
    for (int t = 0; t < T4; t++)
        scale[t] = rsqrtf(s_red[t][0] * (1.f / HDIM) + 1e-5f);

    #pragma unroll
    for (int it = 0; it < HDIM/256; it++) {
        int i = tid + it*256;
        float nw = norm_w[i];
        #pragma unroll
        for (int t = 0; t < T4; t++) {
            float xv = s_t[t][i];
            out[(size_t)(tb + t)*HDIM + i] = xv;            // residual init
            float tv = xv * scale[t] * nw;
            s_t[t][i] = tv;
            g_t[(size_t)(tb + t)*HDIM + i] = __float2half_rn(tv);
        }
    }
    __syncthreads();

    // gate: each warp does 4 experts, reusing each gate_w load for 4 tokens
    for (int e = warp; e < NEXP; e += 8) {
        const float* gw = gate_w + (size_t)e * HDIM;
        float a0 = 0.f, a1 = 0.f, a2 = 0.f, a3 = 0.f;
        for (int i = lane; i < HDIM; i += 32) {
            float g = gw[i];
            a0 += s_t[0][i]*g; a1 += s_t[1][i]*g;
            a2 += s_t[2][i]*g; a3 += s_t[3][i]*g;
        }
        #pragma unroll
        for (int o = 16; o; o >>= 1) {
            a0 += __shfl_down_sync(0xffffffffu, a0, o);
            a1 += __shfl_down_sync(0xffffffffu, a1, o);
            a2 += __shfl_down_sync(0xffffffffu, a2, o);
            a3 += __shfl_down_sync(0xffffffffu, a3, o);
        }
        if (lane == 0) {
            float gb = gate_b[e];
            s_log[0][e] = a0 + gb; s_log[1][e] = a1 + gb;
            s_log[2][e] = a2 + gb; s_log[3][e] = a3 + gb;
        }
    }
    __syncthreads();

    if (tid < T4) {
        int tok = tb + tid;
        int idx[TOPK]; float val[TOPK];
        unsigned mask = 0;
        #pragma unroll
        for (int k = 0; k < TOPK; k++) {
            float best = -1e30f; int bi = 0;
            for (int e = 0; e < NEXP; e++)
                if (!((mask >> e) & 1u) && s_log[tid][e] > best) { best = s_log[tid][e]; bi = e; }
            mask |= 1u << bi; idx[k] = bi; val[k] = best;
        }
        float mx = val[0];
        float se = 0.f;
        #pragma unroll
        for (int k = 0; k < TOPK; k++) { val[k] = expf(val[k] - mx); se += val[k]; }
        float inv = 1.f / se;
        #pragma unroll
        for (int k = 0; k < TOPK; k++) {
            g_topidx[tok*TOPK + k] = idx[k];
            g_topw[tok*TOPK + k]  = val[k] * inv;
            atomicAdd(&g_counts[idx[k]], 1);
        }
    }
}

// ---------------- k2: scan + scatter (single block) ----------------
__global__ __launch_bounds__(1024) void k2_route() {
    __shared__ int s_cur[NEXP];
    __shared__ int s_off[NEXP];
    int tid = threadIdx.x;
    if (tid == 0) {
        int s = 0;
        for (int e = 0; e < NEXP; e++) {
            s_off[e] = s; g_offsets[e] = s; s += g_counts[e];
        }
        g_offsets[NEXP] = s;
    }
    if (tid < NEXP) s_cur[tid] = 0;
    __syncthreads();
    #pragma unroll
    for (int p = 0; p < NSLOT/1024; p++) {
        int i = tid + p*1024;
        int e = g_topidx[i];
        int pos = s_off[e] + atomicAdd(&s_cur[e], 1);
        g_slot_tok[pos] = i >> 2;
        g_slot_w[pos]   = g_topw[i];
    }
}

// ================= k4: dual-subtile fp16 mma GEMM + swiglu =================
__global__ __launch_bounds__(256, 2) void k4_mlp1(
    const int* __restrict__ blocks, const int* __restrict__ scales,
    const float* __restrict__ bias)
{
    int e  = blockIdx.y;
    int nt = blockIdx.z;                  // 2I/BN = 16
    int cnt = g_counts[e];
    int m0 = blockIdx.x * BM;
    if (m0 >= cnt) return;
    bool do2 = (m0 + 64 < cnt);
    int off = g_offsets[e];

    extern __shared__ char dsm[];
    char* sb = (char*)(((uintptr_t)dsm + 1023) & ~(uintptr_t)1023);
    uint32_t sb32 = smem_u32(sb);
    __shared__ int s_tok[BM];

    const int ROWS = 2*IDIM, GRPS = HDIM/32;
    int tid = threadIdx.x;
    int lane = tid & 31, wid = tid >> 5;
    int wm = wid >> 2, wn = wid & 3;

    for (int i = tid; i < BM; i += 256) {
        int m = m0 + i;
        s_tok[i] = (m < cnt) ? g_slot_tok[off + m] : 0;
    }
    __syncthreads();

    int ci[4], cn[4], cj[4];
    #pragma unroll
    for (int p = 0; p < 4; p++) {
        ci[p] = (tid >> 5)*128 + p*32 + lane;
        cn[p] = ci[p] >> 3; cj[p] = ci[p] & 7;
    }
    const int* wbase = blocks + ((size_t)e*ROWS + nt*BN)*(size_t)GRPS*16;
    const int* sbase = scales + ((size_t)e*ROWS + nt*BN)*(size_t)GRPS;

    uint4    rw[4];
    uint32_t scl[4];

    auto issueLdg = [&](int kt) {
        #pragma unroll
        for (int p = 0; p < 4; p++) {
            rw[p] = *(const uint4*)(wbase + (size_t)cn[p]*GRPS*16
                                    + (kt*2 + (cj[p]>>2))*16 + (cj[p]&3)*4);
            scl[p] = (uint32_t)__ldg(sbase + cn[p]*GRPS + kt*2 + (cj[p]>>2));
        }
    };

    auto issueCp = [&](int kt) {
        int s = kt & 1;
        int c = tid & 7, mr = tid >> 3;
        cp16(sb32 + AS_OFF(s) + swz(mr*128 + c*16),
             g_t + (size_t)s_tok[mr]*HDIM + kt*BK + c*8);
        cp16(sb32 + AS_OFF(s) + swz((mr+32)*128 + c*16),
             g_t + (size_t)s_tok[mr+32]*HDIM + kt*BK + c*8);
        if (do2) {
            cp16(sb32 + AS_OFF(s) + swz((mr+64)*128 + c*16),
                 g_t + (size_t)s_tok[mr+64]*HDIM + kt*BK + c*8);
            cp16(sb32 + AS_OFF(s) + swz((mr+96)*128 + c*16),
                 g_t + (size_t)s_tok[mr+96]*HDIM + kt*BK + c*8);
        }
        CP_COMMIT();
    };

    auto decode = [&](int kt) {
        int s = kt & 1;
        #pragma unroll
        for (int p = 0; p < 4; p++) {
            uint32_t sc2 = ((scl[p] - 112u) << 10) * 0x00010001u;
            uint4 o = dec8(rw[p], sc2);
            *(uint4*)(sb + BS_OFF(s) + swz(cn[p]*128 + cj[p]*16)) = o;
        }
    };

    float acc[2][2][4][4] = {};          // [subtile][h][g][4]

    issueCp(0);
    issueLdg(0);
    CP_WAIT0();
    decode(0);

    #pragma unroll 1
    for (int kt = 0; kt < NK; kt++) {
        int s = kt & 1;
        if (kt + 1 < NK) issueLdg(kt + 1);   // regs free; overlaps barrier wait
        __syncthreads();
        if (kt + 1 < NK) issueCp(kt + 1);
        uint32_t Ab = sb32 + AS_OFF(s), Bb = sb32 + BS_OFF(s);
        #pragma unroll
        for (int kk = 0; kk < 4; kk++) {
            uint32_t b[4][2];
            {
                int r = lane & 7, kb = (lane >> 3) & 1, nb = lane >> 4;
                #pragma unroll
                for (int g2 = 0; g2 < 2; g2++) {
                    uint32_t ad = Bb + swz((wn*32 + g2*16 + nb*8 + r)*128 + kk*32 + kb*16);
                    ldsm4(b[2*g2][0], b[2*g2][1], b[2*g2+1][0], b[2*g2+1][1], ad);
                }
            }
            int r = lane & 7, sel = (lane >> 3) & 1, ks = lane >> 4;
            uint32_t a[2][4];
            #pragma unroll
            for (int h = 0; h < 2; h++) {
                uint32_t ad = Ab + swz((wm*32 + h*16 + sel*8 + r)*128 + kk*32 + ks*16);
                ldsm4(a[h][0], a[h][1], a[h][2], a[h][3], ad);
            }
            #pragma unroll
            for (int h = 0; h < 2; h++)
                #pragma unroll
                for (int g = 0; g < 4; g++)
                    mma_fp16(acc[0][h][g], a[h], b[g]);
            if (do2) {
                #pragma unroll
                for (int h = 0; h < 2; h++) {
                    uint32_t ad = Ab + swz((64 + wm*32 + h*16 + sel*8 + r)*128 + kk*32 + ks*16);
                    ldsm4(a[h][0], a[h][1], a[h][2], a[h][3], ad);
                }
                #pragma unroll
                for (int h = 0; h < 2; h++)
                    #pragma unroll
                    for (int g = 0; g < 4; g++)
                        mma_fp16(acc[1][h][g], a[h], b[g]);
            }
        }
        if (kt + 1 < NK) { decode(kt + 1); CP_WAIT0(); }
    }

    // ---- epilogue: bias + swiglu -> g_a (fp16) ----
    #pragma unroll
    for (int t = 0; t < 2; t++) {
        #pragma unroll
        for (int h = 0; h < 2; h++) {
            #pragma unroll
            for (int half = 0; half < 2; half++) {
                int m = m0 + t*64 + wm*32 + h*16 + (lane >> 2) + half*8;
                if (m >= cnt) continue;
                int slot = off + m;
                #pragma unroll
                for (int g = 0; g < 4; g++) {
                    int gcol = nt*BN + wn*32 + g*8 + 2*(lane & 3);
                    float hg = acc[t][h][g][half*2+0] + bias[(size_t)e*ROWS + gcol];
                    float hl = acc[t][h][g][half*2+1] + bias[(size_t)e*ROWS + gcol + 1];
                    hg = fminf(hg, 7.f);
                    hl = fminf(fmaxf(hl, -7.f), 7.f);
                    float aa = hg * (1.f / (1.f + expf(-1.702f * hg))) * (hl + 1.f);
                    g_a[(size_t)slot*IDIM + (gcol >> 1)] = __float2half_rn(aa);
                }
            }
        }
    }
}

// ================= k5: dual-subtile fp16 mma GEMM + weighted scatter =================
__global__ __launch_bounds__(256, 2) void k5_mlp2(
    const int* __restrict__ blocks, const int* __restrict__ scales,
    const float* __restrict__ bias, float* __restrict__ out)
{
    int e  = blockIdx.y;
    int nt = blockIdx.z;                  // H/BN = 8
    int cnt = g_counts[e];
    int m0 = blockIdx.x * BM;
    if (m0 >= cnt) return;
    bool do2 = (m0 + 64 < cnt);
    int off = g_offsets[e];

    extern __shared__ char dsm[];
    char* sb = (char*)(((uintptr_t)dsm + 1023) & ~(uintptr_t)1023);
    uint32_t sb32 = smem_u32(sb);
    __shared__ int   s_tok[BM];
    __shared__ float s_w[BM];

    const int ROWS = HDIM, GRPS = IDIM/32;
    int tid = threadIdx.x;
    int lane = tid & 31, wid = tid >> 5;
    int wm = wid >> 2, wn = wid & 3;

    for (int i = tid; i < BM; i += 256) {
        int m = m0 + i;
        s_tok[i] = (m < cnt) ? g_slot_tok[off + m] : 0;
        s_w[i]   = (m < cnt) ? g_slot_w[off + m] : 0.f;
    }
    __syncthreads();

    int ci[4], cn[4], cj[4];
    #pragma unroll
    for (int p = 0; p < 4; p++) {
        ci[p] = (tid >> 5)*128 + p*32 + lane;
        cn[p] = ci[p] >> 3; cj[p] = ci[p] & 7;
    }
    const int* wbase = blocks + ((size_t)e*ROWS + nt*BN)*(size_t)GRPS*16;
    const int* sbase = scales + ((size_t)e*ROWS + nt*BN)*(size_t)GRPS;

    uint4    rw[4];
    uint32_t scl[4];

    auto issueLdg = [&](int kt) {
        #pragma unroll
        for (int p = 0; p < 4; p++) {
            rw[p] = *(const uint4*)(wbase + (size_t)cn[p]*GRPS*16
                                    + (kt*2 + (cj[p]>>2))*16 + (cj[p]&3)*4);
            scl[p] = (uint32_t)__ldg(sbase + cn[p]*GRPS + kt*2 + (cj[p]>>2));
        }
    };

    auto issueCp = [&](int kt) {
        int s = kt & 1;
        int c = tid & 7, mr = tid >> 3;
        int r0 = off + m0 + mr;       if (r0 > NSLOT-1) r0 = NSLOT-1;
        int r1 = off + m0 + mr + 32;  if (r1 > NSLOT-1) r1 = NSLOT-1;
        cp16(sb32 + AS_OFF(s) + swz(mr*128 + c*16), g_a + (size_t)r0*IDIM + kt*BK + c*8);
        cp16(sb32 + AS_OFF(s) + swz((mr+32)*128 + c*16), g_a + (size_t)r1*IDIM + kt*BK + c*8);
        if (do2) {
            int r2 = off + m0 + mr + 64;  if (r2 > NSLOT-1) r2 = NSLOT-1;
            int r3 = off + m0 + mr + 96;  if (r3 > NSLOT-1) r3 = NSLOT-1;
            cp16(sb32 + AS_OFF(s) + swz((mr+64)*128 + c*16), g_a + (size_t)r2*IDIM + kt*BK + c*8);
            cp16(sb32 + AS_OFF(s) + swz((mr+96)*128 + c*16), g_a + (size_t)r3*IDIM + kt*BK + c*8);
        }
        CP_COMMIT();
    };

    auto decode = [&](int kt) {
        int s = kt & 1;
        #pragma unroll
        for (int p = 0; p < 4; p++) {
            uint32_t sc2 = ((scl[p] - 112u) << 10) * 0x00010001u;
            uint4 o = dec8(rw[p], sc2);
            *(uint4*)(sb + BS_OFF(s) + swz(cn[p]*128 + cj[p]*16)) = o;
        }
    };

    float acc[2][2][4][4] = {};

    issueCp(0);
    issueLdg(0);
    CP_WAIT0();
    decode(0);

    #pragma unroll 1
    for (int kt = 0; kt < NK; kt++) {
        int s = kt & 1;
        if (kt + 1 < NK) issueLdg(kt + 1);
        __syncthreads();
        if (kt + 1 < NK) issueCp(kt + 1);
        uint32_t Ab = sb32 + AS_OFF(s), Bb = sb32 + BS_OFF(s);
        #pragma unroll
        for (int kk = 0; kk < 4; kk++) {
            uint32_t b[4][2];
            {
                int r = lane & 7, kb = (lane >> 3) & 1, nb = lane >> 4;
                #pragma unroll
                for (int g2 = 0; g2 < 2; g2++) {
                    uint32_t ad = Bb + swz((wn*32 + g2*16 + nb*8 + r)*128 + kk*32 + kb*16);
                    ldsm4(b[2*g2][0], b[2*g2][1], b[2*g2+1][0], b[2*g2+1][1], ad);
                }
            }
            int r = lane & 7, sel = (lane >> 3) & 1, ks = lane >> 4;
            uint32_t a[2][4];
            #pragma unroll
            for (int h = 0; h < 2; h++) {
                uint32_t ad = Ab + swz((wm*32 + h*16 + sel*8 + r)*128 + kk*32 + ks*16);
                ldsm4(a[h][0], a[h][1], a[h][2], a[h][3], ad);
            }
            #pragma unroll
            for (int h = 0; h < 2; h++)
                #pragma unroll
                for (int g = 0; g < 4; g++)
                    mma_fp16(acc[0][h][g], a[h], b[g]);
            if (do2) {
                #pragma unroll
                for (int h = 0; h < 2; h++) {
                    uint32_t ad = Ab + swz((64 + wm*32 + h*16 + sel*8 + r)*128 + kk*32 + ks*16);
                    ldsm4(a[h][0], a[h][1], a[h][2], a[h][3], ad);
                }
                #pragma unroll
                for (int h = 0; h < 2; h++)
                    #pragma unroll
                    for (int g = 0; g < 4; g++)
                        mma_fp16(acc[1][h][g], a[h], b[g]);
            }
        }
        if (kt + 1 < NK) { decode(kt + 1); CP_WAIT0(); }
    }

    #pragma unroll
    for (int t = 0; t < 2; t++) {
        #pragma unroll
        for (int h = 0; h < 2; h++) {
            #pragma unroll
            for (int half = 0; half < 2; half++) {
                int mi = t*64 + wm*32 + h*16 + (lane >> 2) + half*8;
                if (m0 + mi >= cnt) continue;
                int tok = s_tok[mi];
                float rwt = s_w[mi];
                #pragma unroll
                for (int g = 0; g < 4; g++) {
                    int gcol = nt*BN + wn*32 + g*8 + 2*(lane & 3);
                    float y0 = acc[t][h][g][half*2+0] + bias[(size_t)e*HDIM + gcol];
                    float y1 = acc[t][h][g][half*2+1] + bias[(size_t)e*HDIM + gcol + 1];
                    atomicAdd(&out[(size_t)tok*HDIM + gcol],     rwt * y0);
                    atomicAdd(&out[(size_t)tok*HDIM + gcol + 1], rwt * y1);
                }
            }
        }
    }
}

// ---------------- launch ----------------
extern "C" void kernel_launch(void* const* d_in, const int* in_sizes, int n_in,
                              void* d_out, int out_size)
{
    const float* x          = (const float*)d_in[0];
    const float* norm_w     = (const float*)d_in[1];
    const float* gate_w     = (const float*)d_in[2];
    const float* gate_b     = (const float*)d_in[3];
    const float* mlp1_bias  = (const float*)d_in[4];
    const float* mlp2_bias  = (const float*)d_in[5];
    const int*   mlp1_blocks= (const int*)d_in[6];
    const int*   mlp1_scales= (const int*)d_in[7];
    const int*   mlp2_blocks= (const int*)d_in[8];
    const int*   mlp2_scales= (const int*)d_in[9];
    float* out = (float*)d_out;

    cudaFuncSetAttribute(k4_mlp1, cudaFuncAttributeMaxDynamicSharedMemorySize, DSMEM_BYTES);
    cudaFuncSetAttribute(k5_mlp2, cudaFuncAttributeMaxDynamicSharedMemorySize, DSMEM_BYTES);

    k0_zero<<<1, 32>>>();
    k1_norm_gate<<<N_TOK/T4, 256>>>(x, norm_w, gate_w, gate_b, out);
    k2_route<<<1, 1024>>>();
    dim3 g4(N_TOK/BM, NEXP, (2*IDIM)/BN);   // (8, 32, 16)
    k4_mlp1<<<g4, 256, DSMEM_BYTES>>>(mlp1_blocks, mlp1_scales, mlp1_bias);
    dim3 g5(N_TOK/BM, NEXP, HDIM/BN);       // (8, 32, 8)
    k5_mlp2<<<g5, 256, DSMEM_BYTES>>>(mlp2_blocks, mlp2_scales, mlp2_bias, out);
}